// round 15
// baseline (speedup 1.0000x reference)
#include <cuda_runtime.h>
#include <cuda_bf16.h>
#include <cuda_fp16.h>
#include <math.h>
#include <stdint.h>

#define NB    8192
#define FEAT  4096
#define MID   512
#define EMB   256
#define KCODE 512

typedef __nv_bfloat16 bf16;
typedef __half fp16;

// ------------- scratch (__device__ globals; no allocs allowed) -------------
__device__ bf16 g_x_hi[NB*FEAT],  g_x_lo[NB*FEAT];
__device__ bf16 g_w1t_hi[MID*FEAT], g_w1t_lo[MID*FEAT];   // enc_w1^T [512,4096]
__device__ bf16 g_w2t_hi[EMB*MID],  g_w2t_lo[EMB*MID];    // enc_w2^T [256,512]
__device__ fp16 g_d1t_hi[MID*EMB];                        // dec_w1^T fp16 (hi only)
__device__ fp16 g_d2t_hi[FEAT*MID];                       // dec_w2^T fp16 (hi only)
__device__ bf16 g_emb_hi[KCODE*EMB], g_emb_lo[KCODE*EMB];
__device__ bf16 g_h_hi[NB*MID],  g_h_lo[NB*MID];
__device__ bf16 g_e_hi[NB*EMB],  g_e_lo[NB*EMB];
__device__ fp16 g_v_hi[NB*EMB];
__device__ fp16 g_dd_hi[NB*MID];
__device__ float g_pv[NB*2];        // per-row per-n-tile argmax value
__device__ int   g_pi[NB*2];        // per-row per-n-tile argmax index
__device__ float g_invn[KCODE];

// ------------- helpers -------------
__device__ __forceinline__ uint32_t smem_u32(const void* p) {
    uint32_t a;
    asm("{ .reg .u64 t; cvta.to.shared.u64 t, %1; cvt.u32.u64 %0, t; }" : "=r"(a) : "l"(p));
    return a;
}
#define SWZ(o) ((o) ^ (((o) >> 3) & 0x70))
#define CP16(dst, src) asm volatile("cp.async.cg.shared.global [%0], [%1], 16;" :: "r"(dst), "l"(src))
#define CP_COMMIT() asm volatile("cp.async.commit_group;" ::: "memory")

__device__ __forceinline__ void ldsm4(uint32_t* r, uint32_t addr) {
    asm volatile("ldmatrix.sync.aligned.m8n8.x4.shared.b16 {%0,%1,%2,%3}, [%4];"
        : "=r"(r[0]), "=r"(r[1]), "=r"(r[2]), "=r"(r[3]) : "r"(addr));
}
template<typename T>
__device__ __forceinline__ void mma16816(float* c, const uint32_t* a, const uint32_t* b);
template<>
__device__ __forceinline__ void mma16816<bf16>(float* c, const uint32_t* a, const uint32_t* b) {
    asm volatile("mma.sync.aligned.m16n8k16.row.col.f32.bf16.bf16.f32 "
        "{%0,%1,%2,%3}, {%4,%5,%6,%7}, {%8,%9}, {%0,%1,%2,%3};"
        : "+f"(c[0]), "+f"(c[1]), "+f"(c[2]), "+f"(c[3])
        : "r"(a[0]), "r"(a[1]), "r"(a[2]), "r"(a[3]), "r"(b[0]), "r"(b[1]));
}
template<>
__device__ __forceinline__ void mma16816<fp16>(float* c, const uint32_t* a, const uint32_t* b) {
    asm volatile("mma.sync.aligned.m16n8k16.row.col.f32.f16.f16.f32 "
        "{%0,%1,%2,%3}, {%4,%5,%6,%7}, {%8,%9}, {%0,%1,%2,%3};"
        : "+f"(c[0]), "+f"(c[1]), "+f"(c[2]), "+f"(c[3])
        : "r"(a[0]), "r"(a[1]), "r"(a[2]), "r"(a[3]), "r"(b[0]), "r"(b[1]));
}

template<typename T> __device__ __forceinline__ void split2(float v, T& h, T& l);
template<> __device__ __forceinline__ void split2<bf16>(float v, bf16& h, bf16& l) {
    h = __float2bfloat16(v);
    l = __float2bfloat16(v - __bfloat162float(h));
}
template<> __device__ __forceinline__ void split2<fp16>(float v, fp16& h, fp16& l) {
    h = __float2half(v);
    l = __float2half(v - __half2float(h));
}
template<typename T>
__device__ __forceinline__ uint32_t pk2(T a, T b) {
    uint32_t u;
    uint16_t* p = (uint16_t*)&u;
    p[0] = *(uint16_t*)&a; p[1] = *(uint16_t*)&b;
    return u;
}

// ============================================================
// split GEMM on HMMA:  C[M,N] = act(A @ W + bias)
// A = (Ah,Al) [M,K] T ; B = (Bh,Bl) [N,K] T (W^T).
// PASSES==3: Ah*Bh + Al*Bh + Ah*Bl ; PASSES==1: Ah*Bh.
// BMT x 256 tile, BK=64, 256 threads; warp grid 2x4 (warp tile BMT/2 x 64).
// 2-stage cp.async double buffer; one sync per chunk. OCC = CTAs/SM hint.
// AMAX: fused per-row scaled-argmax epilogue (for the sim GEMM); emits one
//       (val, idx) candidate per row per n-tile into pv/pi instead of C.
// ============================================================
#define BN 256
#define BK 64

template<typename T, int PASSES, int BMT>
__device__ __forceinline__ void load_chunk(
    uint32_t st, const T* __restrict__ Ah, const T* __restrict__ Al,
    const T* __restrict__ Bh, const T* __restrict__ Bl,
    int m0, int n0, int k0, int K, int tid)
{
    constexpr uint32_t OFF_AL = (uint32_t)BMT * 128;
    constexpr uint32_t OFF_BH = (PASSES == 3) ? 2u * BMT * 128 : (uint32_t)BMT * 128;
    constexpr uint32_t OFF_BL = OFF_BH + 32768;
    const T* pAh = Ah + (size_t)m0 * K + k0;
    #pragma unroll
    for (int i = 0; i < BMT / 32; i++) {      // BMT rows x 8 x 16B
        int u = i * 256 + tid;
        int r = u >> 3, c = u & 7;
        uint32_t so = SWZ((uint32_t)(r * 128 + c * 16));
        size_t go = (size_t)r * K + c * 8;
        CP16(st + so, pAh + go);
        if (PASSES == 3) {
            const T* pAl = Al + (size_t)m0 * K + k0;
            CP16(st + OFF_AL + so, pAl + go);
        }
    }
    const T* pBh = Bh + (size_t)n0 * K + k0;
    #pragma unroll
    for (int i = 0; i < 8; i++) {             // B: 256 rows x 8 x 16B
        int u = i * 256 + tid;
        int r = u >> 3, c = u & 7;
        uint32_t so = SWZ((uint32_t)(r * 128 + c * 16));
        size_t go = (size_t)r * K + c * 8;
        CP16(st + OFF_BH + so, pBh + go);
        if (PASSES == 3) {
            const T* pBl = Bl + (size_t)n0 * K + k0;
            CP16(st + OFF_BL + so, pBl + go);
        }
    }
}

template<typename T, int PASSES, int BMT>
__device__ __forceinline__ void compute_chunk(
    float (&acc)[BMT / 32][8][4], uint32_t st, int wm, int wn, int g, int lr)
{
    constexpr int MT = BMT / 32;
    constexpr uint32_t OFF_AL = (uint32_t)BMT * 128;
    constexpr uint32_t OFF_BH = (PASSES == 3) ? 2u * BMT * 128 : (uint32_t)BMT * 128;
    constexpr uint32_t OFF_BL = OFF_BH + 32768;
    #pragma unroll
    for (int ks = 0; ks < 4; ks++) {
        uint32_t afh[MT * 4], afl[MT * 4], bfr[16];
        #pragma unroll
        for (int mt = 0; mt < MT; mt++) {
            int row = wm * (BMT / 2) + mt * 16 + (g & 1) * 8 + lr;
            int k   = ks * 16 + (g >> 1) * 8;
            uint32_t off = SWZ((uint32_t)(row * 128 + k * 2));
            ldsm4(&afh[mt * 4], st + off);
            if (PASSES == 3) ldsm4(&afl[mt * 4], st + OFF_AL + off);
        }
        #pragma unroll
        for (int p = 0; p < 4; p++) {
            int row = wn * 64 + (p * 2 + (g >> 1)) * 8 + lr;
            int k   = ks * 16 + (g & 1) * 8;
            uint32_t off = SWZ((uint32_t)(row * 128 + k * 2));
            ldsm4(&bfr[p * 4], st + OFF_BH + off);
        }
        #pragma unroll
        for (int mt = 0; mt < MT; mt++)
            #pragma unroll
            for (int nt = 0; nt < 8; nt++)
                mma16816<T>(acc[mt][nt], &afh[mt * 4], &bfr[(nt >> 1) * 4 + (nt & 1) * 2]);
        if (PASSES == 3) {
            #pragma unroll
            for (int mt = 0; mt < MT; mt++)
                #pragma unroll
                for (int nt = 0; nt < 8; nt++)
                    mma16816<T>(acc[mt][nt], &afl[mt * 4], &bfr[(nt >> 1) * 4 + (nt & 1) * 2]);
            #pragma unroll
            for (int p = 0; p < 4; p++) {
                int row = wn * 64 + (p * 2 + (g >> 1)) * 8 + lr;
                int k   = ks * 16 + (g & 1) * 8;
                uint32_t off = SWZ((uint32_t)(row * 128 + k * 2));
                ldsm4(&bfr[p * 4], st + OFF_BL + off);
            }
            #pragma unroll
            for (int mt = 0; mt < MT; mt++)
                #pragma unroll
                for (int nt = 0; nt < 8; nt++)
                    mma16816<T>(acc[mt][nt], &afh[mt * 4], &bfr[(nt >> 1) * 4 + (nt & 1) * 2]);
        }
    }
}

template<bool RELU, bool HASBIAS, bool WF32, bool WH, bool WLO, bool AMAX,
         int BMT, int OCC, typename T, int PASSES>
__global__ __launch_bounds__(256, OCC)
void tgemm(const T* __restrict__ Ah, const T* __restrict__ Al,
           const T* __restrict__ Bh, const T* __restrict__ Bl,
           const float* __restrict__ bias,
           float* __restrict__ oF, T* __restrict__ oH, T* __restrict__ oL,
           const float* __restrict__ pinv, float* __restrict__ pv,
           int* __restrict__ pi,
           int M, int N, int K)
{
    constexpr int MT = BMT / 32;
    constexpr uint32_t STAGE = (PASSES == 3) ? (2u * BMT * 128 + 65536)
                                             : ((uint32_t)BMT * 128 + 32768);
    extern __shared__ char smem[];
    const uint32_t sb = smem_u32(smem);
    const int tid  = threadIdx.x;
    const int wid  = tid >> 5;
    const int lane = tid & 31;
    const int wm   = wid >> 2;
    const int wn   = wid & 3;
    const int m0   = blockIdx.y * BMT;
    const int n0   = blockIdx.x * BN;
    const int NC   = K / BK;
    const int g    = lane >> 3;
    const int lr   = lane & 7;

    float acc[MT][8][4];
    #pragma unroll
    for (int i = 0; i < MT; i++)
        #pragma unroll
        for (int j = 0; j < 8; j++)
            #pragma unroll
            for (int k = 0; k < 4; k++) acc[i][j][k] = 0.f;

    load_chunk<T, PASSES, BMT>(sb, Ah, Al, Bh, Bl, m0, n0, 0, K, tid);
    CP_COMMIT();

    #pragma unroll 1
    for (int c = 0; c < NC; c++) {
        asm volatile("cp.async.wait_group 0;" ::: "memory");
        __syncthreads();
        if (c + 1 < NC)
            load_chunk<T, PASSES, BMT>(sb + ((c + 1) & 1) * STAGE,
                                       Ah, Al, Bh, Bl, m0, n0, (c + 1) * BK, K, tid);
        CP_COMMIT();
        compute_chunk<T, PASSES, BMT>(acc, sb + (c & 1) * STAGE, wm, wn, g, lr);
    }

    const int r0 = lane >> 2;
    const int c0 = (lane & 3) * 2;

    if (AMAX) {
        // ---- fused scaled-argmax epilogue: one (val,idx) per row per n-tile ----
        __syncthreads();                      // all warps done reading smem stages
        float* sval = (float*)smem;           // [BMT][4]
        int*   sidx = (int*)(smem + (size_t)BMT * 4 * sizeof(float));
        const int lgrp = lane & 3;
        #pragma unroll
        for (int mt = 0; mt < MT; mt++) {
            #pragma unroll
            for (int half = 0; half < 2; half++) {
                float bv = -3.402823466e+38f; int bidx = 0;
                #pragma unroll
                for (int nt = 0; nt < 8; nt++) {
                    int col = n0 + wn * 64 + nt * 8 + c0;
                    float v0 = acc[mt][nt][half * 2 + 0] * __ldg(&pinv[col]);
                    float v1 = acc[mt][nt][half * 2 + 1] * __ldg(&pinv[col + 1]);
                    if (v0 > bv) { bv = v0; bidx = col; }
                    if (v1 > bv) { bv = v1; bidx = col + 1; }
                }
                #pragma unroll
                for (int m = 1; m < 4; m <<= 1) {
                    float ov = __shfl_xor_sync(0xFFFFFFFFu, bv, m);
                    int   oi = __shfl_xor_sync(0xFFFFFFFFu, bidx, m);
                    if (ov > bv || (ov == bv && oi < bidx)) { bv = ov; bidx = oi; }
                }
                if (lgrp == 0) {
                    int rl = wm * (BMT / 2) + mt * 16 + r0 + half * 8;
                    sval[rl * 4 + wn] = bv;
                    sidx[rl * 4 + wn] = bidx;
                }
            }
        }
        __syncthreads();
        if (tid < BMT) {
            float bv = sval[tid * 4]; int bidx = sidx[tid * 4];
            #pragma unroll
            for (int q = 1; q < 4; q++) {
                float ov = sval[tid * 4 + q]; int oi = sidx[tid * 4 + q];
                if (ov > bv || (ov == bv && oi < bidx)) { bv = ov; bidx = oi; }
            }
            int row = m0 + tid;
            pv[row * 2 + blockIdx.x] = bv;
            pi[row * 2 + blockIdx.x] = bidx;
        }
        return;
    }

    // ---- standard epilogue ----
    #pragma unroll
    for (int nt = 0; nt < 8; nt++) {
        int col = n0 + wn * 64 + nt * 8 + c0;
        float b0 = 0.f, b1 = 0.f;
        if (HASBIAS) { b0 = __ldg(&bias[col]); b1 = __ldg(&bias[col + 1]); }
        #pragma unroll
        for (int mt = 0; mt < MT; mt++) {
            int rowa = m0 + wm * (BMT / 2) + mt * 16 + r0;
            float v0 = acc[mt][nt][0] + b0;
            float v1 = acc[mt][nt][1] + b1;
            float v2 = acc[mt][nt][2] + b0;
            float v3 = acc[mt][nt][3] + b1;
            if (RELU) {
                v0 = fmaxf(v0, 0.f); v1 = fmaxf(v1, 0.f);
                v2 = fmaxf(v2, 0.f); v3 = fmaxf(v3, 0.f);
            }
            size_t oa = (size_t)rowa * N + col;
            size_t ob = (size_t)(rowa + 8) * N + col;
            if (WF32) {
                *(float2*)(oF + oa) = make_float2(v0, v1);
                *(float2*)(oF + ob) = make_float2(v2, v3);
            }
            if (WH) {
                T h0, h1, h2, h3, l0, l1, l2, l3;
                split2<T>(v0, h0, l0); split2<T>(v1, h1, l1);
                split2<T>(v2, h2, l2); split2<T>(v3, h3, l3);
                *(uint32_t*)(oH + oa) = pk2(h0, h1);
                *(uint32_t*)(oH + ob) = pk2(h2, h3);
                if (WLO) {
                    *(uint32_t*)(oL + oa) = pk2(l0, l1);
                    *(uint32_t*)(oL + ob) = pk2(l2, l3);
                }
            }
        }
    }
}

// ============================================================
// fp32 -> (hi, lo) split, float4-vectorized (x only)
// ============================================================
__global__ __launch_bounds__(256)
void split_kernel(const float4* __restrict__ in, bf16* __restrict__ hi,
                  bf16* __restrict__ lo, int n4)
{
    int i = blockIdx.x * 256 + threadIdx.x;
    if (i >= n4) return;
    float4 v = in[i];
    bf16 h0, h1, h2, h3, l0, l1, l2, l3;
    split2<bf16>(v.x, h0, l0); split2<bf16>(v.y, h1, l1);
    split2<bf16>(v.z, h2, l2); split2<bf16>(v.w, h3, l3);
    *(uint32_t*)(hi + (size_t)i * 4)     = pk2(h0, h1);
    *(uint32_t*)(hi + (size_t)i * 4 + 2) = pk2(h2, h3);
    *(uint32_t*)(lo + (size_t)i * 4)     = pk2(l0, l1);
    *(uint32_t*)(lo + (size_t)i * 4 + 2) = pk2(l2, l3);
}

// ============================================================
// merged emb prep: split emb -> bf16 hi/lo AND inverse row norms
// ============================================================
__global__ __launch_bounds__(256)
void emb_prep_kernel(const float* __restrict__ emb, bf16* __restrict__ hi,
                     bf16* __restrict__ lo, float* __restrict__ invn)
{
    int c = blockIdx.x, t = threadIdx.x;
    float v = emb[(size_t)c * EMB + t];
    bf16 h, l;
    split2<bf16>(v, h, l);
    hi[(size_t)c * EMB + t] = h;
    lo[(size_t)c * EMB + t] = l;
    __shared__ float red[256];
    red[t] = v * v;
    __syncthreads();
    #pragma unroll
    for (int off = 128; off > 0; off >>= 1) {
        if (t < off) red[t] += red[t + off];
        __syncthreads();
    }
    if (t == 0) invn[c] = 1.f / (sqrtf(red[0]) + 1e-12f);
}

// ============================================================
// transpose + split: in [R,C] fp32 -> hi (and optionally lo) [C,R] T
// ============================================================
template<typename T, bool WANTLO>
__global__ __launch_bounds__(256)
void tsplit_kernel(const float* __restrict__ in, T* __restrict__ hi,
                   T* __restrict__ lo, int R, int C)
{
    __shared__ float t[32][33];
    int r0 = blockIdx.x * 32, c0 = blockIdx.y * 32;
    int tx = threadIdx.x, ty = threadIdx.y;
    #pragma unroll
    for (int i = 0; i < 32; i += 8)
        t[ty + i][tx] = in[(size_t)(r0 + ty + i) * C + c0 + tx];
    __syncthreads();
    #pragma unroll
    for (int i = 0; i < 32; i += 8) {
        float v = t[tx][ty + i];
        T h, l;
        split2<T>(v, h, l);
        size_t o = (size_t)(c0 + ty + i) * R + r0 + tx;
        hi[o] = h;
        if (WANTLO) lo[o] = l;
    }
}

// ============================================================
// VQ finalize: pick best of 2 per-tile candidates, write onehot + gather
// (tile0 wins ties -> lower index, matching jnp.argmax)
// ============================================================
__global__ __launch_bounds__(256)
void vq_kernel(const float* __restrict__ pv, const int* __restrict__ pi,
               const float* __restrict__ emb,
               float* __restrict__ vq_feat, float* __restrict__ onehot,
               fp16* __restrict__ vq_hi)
{
    const int w    = threadIdx.x >> 5;
    const int lane = threadIdx.x & 31;
    const int row  = blockIdx.x * 8 + w;

    float v0 = __ldg(&pv[row * 2]);
    float v1 = __ldg(&pv[row * 2 + 1]);
    int bi = (v1 > v0) ? __ldg(&pi[row * 2 + 1]) : __ldg(&pi[row * 2]);

    float* oh = onehot + (size_t)row * KCODE;
    #pragma unroll
    for (int i = 0; i < 16; i++) {
        int idx = i * 32 + lane;
        oh[idx] = (idx == bi) ? 1.f : 0.f;
    }
    const float* er = emb + (size_t)bi * EMB;
    float* vf = vq_feat + (size_t)row * EMB;
    fp16* vh = vq_hi + (size_t)row * EMB;
    #pragma unroll
    for (int i = 0; i < 8; i++) {
        int c = i * 32 + lane;
        float ev = er[c];
        vf[c] = ev;
        vh[c] = __float2half(ev);
    }
}

// ============================================================
// launcher
// ============================================================
extern "C" void kernel_launch(void* const* d_in, const int* in_sizes, int n_in,
                              void* d_out, int out_size)
{
    const float* x      = (const float*)d_in[0];
    const float* enc_w1 = (const float*)d_in[1];
    const float* enc_b1 = (const float*)d_in[2];
    const float* enc_w2 = (const float*)d_in[3];
    const float* enc_b2 = (const float*)d_in[4];
    const float* emb    = (const float*)d_in[5];
    const float* dec_w1 = (const float*)d_in[6];
    const float* dec_b1 = (const float*)d_in[7];
    const float* dec_w2 = (const float*)d_in[8];
    const float* dec_b2 = (const float*)d_in[9];

    float* out = (float*)d_out;
    float* o_encoded = out;
    float* o_vqfeat  = o_encoded + (size_t)NB * EMB;
    float* o_onehot  = o_vqfeat  + (size_t)NB * EMB;
    float* o_decoded = o_onehot  + (size_t)NB * KCODE;
    float* o_emb     = o_decoded + (size_t)NB * FEAT;

    bf16 *x_hi, *x_lo, *w1t_hi, *w1t_lo, *w2t_hi, *w2t_lo, *emb_hi, *emb_lo,
         *h_hi, *h_lo, *e_hi, *e_lo;
    fp16 *d1t_hi, *d2t_hi, *v_hi, *dd_hi;
    float *pv, *invn; int *pi;
    cudaGetSymbolAddress((void**)&x_hi, g_x_hi);     cudaGetSymbolAddress((void**)&x_lo, g_x_lo);
    cudaGetSymbolAddress((void**)&w1t_hi, g_w1t_hi); cudaGetSymbolAddress((void**)&w1t_lo, g_w1t_lo);
    cudaGetSymbolAddress((void**)&w2t_hi, g_w2t_hi); cudaGetSymbolAddress((void**)&w2t_lo, g_w2t_lo);
    cudaGetSymbolAddress((void**)&d1t_hi, g_d1t_hi);
    cudaGetSymbolAddress((void**)&d2t_hi, g_d2t_hi);
    cudaGetSymbolAddress((void**)&emb_hi, g_emb_hi); cudaGetSymbolAddress((void**)&emb_lo, g_emb_lo);
    cudaGetSymbolAddress((void**)&h_hi, g_h_hi);     cudaGetSymbolAddress((void**)&h_lo, g_h_lo);
    cudaGetSymbolAddress((void**)&e_hi, g_e_hi);     cudaGetSymbolAddress((void**)&e_lo, g_e_lo);
    cudaGetSymbolAddress((void**)&v_hi, g_v_hi);
    cudaGetSymbolAddress((void**)&dd_hi, g_dd_hi);
    cudaGetSymbolAddress((void**)&pv, g_pv);         cudaGetSymbolAddress((void**)&pi, g_pi);
    cudaGetSymbolAddress((void**)&invn, g_invn);

    const int SM_G1  = 2 * 98304;   // BMT=128 3-pass 2 stages
    const int SM_G2  = 2 * 81920;   // BMT=64  3-pass 2 stages
    const int SM_P1  = 2 * 40960;   // BMT=64  1-pass 2 stages (2 CTAs/SM)
    cudaFuncSetAttribute(tgemm<true,  true,  false, true,  true,  false, 128, 1, bf16, 3>, cudaFuncAttributeMaxDynamicSharedMemorySize, SM_G1);
    cudaFuncSetAttribute(tgemm<false, true,  true,  true,  true,  false, 64,  1, bf16, 3>, cudaFuncAttributeMaxDynamicSharedMemorySize, SM_G2);
    cudaFuncSetAttribute(tgemm<false, false, false, false, false, true,  128, 1, bf16, 3>, cudaFuncAttributeMaxDynamicSharedMemorySize, SM_G1);
    cudaFuncSetAttribute(tgemm<true,  true,  false, true,  false, false, 64,  2, fp16, 1>, cudaFuncAttributeMaxDynamicSharedMemorySize, SM_P1);
    cudaFuncSetAttribute(tgemm<true,  true,  true,  false, false, false, 64,  2, fp16, 1>, cudaFuncAttributeMaxDynamicSharedMemorySize, SM_P1);

    // launches ordered so GEMM1 is the 4th kernel launch (profiler capture slot)
    // 1) x split
    split_kernel<<<(NB * FEAT / 4) / 256, 256>>>((const float4*)x, x_hi, x_lo, NB * FEAT / 4);
    // 2) enc_w1^T split
    tsplit_kernel<bf16, true><<<dim3(FEAT / 32, MID / 32),  dim3(32, 8)>>>(enc_w1, w1t_hi, w1t_lo, FEAT, MID);
    // 3) emb split + inv norms (merged)
    emb_prep_kernel<<<KCODE, 256>>>(emb, emb_hi, emb_lo, invn);
    // 4) GEMM1: h = relu(x @ enc_w1 + b1)  [PROFILE TARGET]
    tgemm<true, true, false, true, true, false, 128, 1, bf16, 3><<<dim3(MID / BN, NB / 128), 256, SM_G1>>>(
        x_hi, x_lo, w1t_hi, w1t_lo, enc_b1, nullptr, h_hi, h_lo,
        nullptr, nullptr, nullptr, NB, MID, FEAT);
    // 5) enc_w2^T split
    tsplit_kernel<bf16, true><<<dim3(MID / 32,  EMB / 32),  dim3(32, 8)>>>(enc_w2, w2t_hi, w2t_lo, MID,  EMB);
    // 6) GEMM2 (BMT=64): encoded = h @ enc_w2 + b2
    tgemm<false, true, true, true, true, false, 64, 1, bf16, 3><<<dim3(EMB / BN, NB / 64), 256, SM_G2>>>(
        h_hi, h_lo, w2t_hi, w2t_lo, enc_b2, o_encoded, e_hi, e_lo,
        nullptr, nullptr, nullptr, NB, EMB, MID);
    // 7) sim GEMM + fused scaled-argmax -> (pv, pi) candidates
    tgemm<false, false, false, false, false, true, 128, 1, bf16, 3><<<dim3(KCODE / BN, NB / 128), 256, SM_G1>>>(
        e_hi, e_lo, emb_hi, emb_lo, nullptr, nullptr, nullptr, nullptr,
        invn, pv, pi, NB, KCODE, EMB);
    // 8) VQ finalize (warp per row: pick of 2 + onehot + gather)
    vq_kernel<<<NB / 8, 256>>>(pv, pi, emb, o_vqfeat, o_onehot, v_hi);
    // 9) dec_w1^T (fp16, hi only)
    tsplit_kernel<fp16, false><<<dim3(EMB / 32,  MID / 32),  dim3(32, 8)>>>(dec_w1, d1t_hi, nullptr, EMB,  MID);
    // 10) GEMM4: d = relu(vq @ dec_w1 + b1)  (1-pass fp16, 2 CTAs/SM)
    tgemm<true, true, false, true, false, false, 64, 2, fp16, 1><<<dim3(MID / BN, NB / 64), 256, SM_P1>>>(
        v_hi, nullptr, d1t_hi, nullptr, dec_b1, nullptr, dd_hi, nullptr,
        nullptr, nullptr, nullptr, NB, MID, EMB);
    // 11) dec_w2^T (fp16, hi only)
    tsplit_kernel<fp16, false><<<dim3(MID / 32,  FEAT / 32), dim3(32, 8)>>>(dec_w2, d2t_hi, nullptr, MID,  FEAT);
    // 12) GEMM5: decoded = relu(d @ dec_w2 + b2)  (1-pass fp16, 2 CTAs/SM)
    tgemm<true, true, true, false, false, false, 64, 2, fp16, 1><<<dim3(FEAT / BN, NB / 64), 256, SM_P1>>>(
        dd_hi, nullptr, d2t_hi, nullptr, dec_b2, o_decoded, nullptr, nullptr,
        nullptr, nullptr, nullptr, NB, FEAT, MID);
    // 13) emb passthrough
    cudaMemcpyAsync(o_emb, emb, (size_t)KCODE * EMB * sizeof(float),
                    cudaMemcpyDeviceToDevice, 0);
}

// round 17
// speedup vs baseline: 1.6967x; 1.6967x over previous
#include <cuda_runtime.h>
#include <cuda_bf16.h>
#include <cuda_fp16.h>
#include <math.h>
#include <stdint.h>

#define NB    8192
#define FEAT  4096
#define MID   512
#define EMB   256
#define KCODE 512

typedef __nv_bfloat16 bf16;
typedef __half fp16;

// ------------- scratch (__device__ globals; no allocs allowed) -------------
__device__ bf16 g_x_hi[NB*FEAT],  g_x_lo[NB*FEAT];
__device__ bf16 g_w1t_hi[MID*FEAT], g_w1t_lo[MID*FEAT];   // enc_w1^T [512,4096]
__device__ bf16 g_w2t_hi[EMB*MID],  g_w2t_lo[EMB*MID];    // enc_w2^T [256,512]
__device__ fp16 g_d1t_hi[MID*EMB];                        // dec_w1^T fp16 (hi only)
__device__ fp16 g_d2t_hi[FEAT*MID];                       // dec_w2^T fp16 (hi only)
__device__ bf16 g_emb_hi[KCODE*EMB], g_emb_lo[KCODE*EMB];
__device__ bf16 g_h_hi[NB*MID],  g_h_lo[NB*MID];
__device__ bf16 g_e_hi[NB*EMB],  g_e_lo[NB*EMB];
__device__ fp16 g_v_hi[NB*EMB];
__device__ fp16 g_dd_hi[NB*MID];
__device__ float g_pv[NB*2];        // per-row per-n-tile argmax value
__device__ int   g_pi[NB*2];        // per-row per-n-tile argmax index
__device__ float g_invn[KCODE];

// ------------- helpers -------------
__device__ __forceinline__ uint32_t smem_u32(const void* p) {
    uint32_t a;
    asm("{ .reg .u64 t; cvta.to.shared.u64 t, %1; cvt.u32.u64 %0, t; }" : "=r"(a) : "l"(p));
    return a;
}
#define SWZ(o) ((o) ^ (((o) >> 3) & 0x70))
#define CP16(dst, src) asm volatile("cp.async.cg.shared.global [%0], [%1], 16;" :: "r"(dst), "l"(src))
#define CP_COMMIT() asm volatile("cp.async.commit_group;" ::: "memory")

__device__ __forceinline__ void ldsm4(uint32_t* r, uint32_t addr) {
    asm volatile("ldmatrix.sync.aligned.m8n8.x4.shared.b16 {%0,%1,%2,%3}, [%4];"
        : "=r"(r[0]), "=r"(r[1]), "=r"(r[2]), "=r"(r[3]) : "r"(addr));
}
template<typename T>
__device__ __forceinline__ void mma16816(float* c, const uint32_t* a, const uint32_t* b);
template<>
__device__ __forceinline__ void mma16816<bf16>(float* c, const uint32_t* a, const uint32_t* b) {
    asm volatile("mma.sync.aligned.m16n8k16.row.col.f32.bf16.bf16.f32 "
        "{%0,%1,%2,%3}, {%4,%5,%6,%7}, {%8,%9}, {%0,%1,%2,%3};"
        : "+f"(c[0]), "+f"(c[1]), "+f"(c[2]), "+f"(c[3])
        : "r"(a[0]), "r"(a[1]), "r"(a[2]), "r"(a[3]), "r"(b[0]), "r"(b[1]));
}
template<>
__device__ __forceinline__ void mma16816<fp16>(float* c, const uint32_t* a, const uint32_t* b) {
    asm volatile("mma.sync.aligned.m16n8k16.row.col.f32.f16.f16.f32 "
        "{%0,%1,%2,%3}, {%4,%5,%6,%7}, {%8,%9}, {%0,%1,%2,%3};"
        : "+f"(c[0]), "+f"(c[1]), "+f"(c[2]), "+f"(c[3])
        : "r"(a[0]), "r"(a[1]), "r"(a[2]), "r"(a[3]), "r"(b[0]), "r"(b[1]));
}

template<typename T> __device__ __forceinline__ void split2(float v, T& h, T& l);
template<> __device__ __forceinline__ void split2<bf16>(float v, bf16& h, bf16& l) {
    h = __float2bfloat16(v);
    l = __float2bfloat16(v - __bfloat162float(h));
}
template<> __device__ __forceinline__ void split2<fp16>(float v, fp16& h, fp16& l) {
    h = __float2half(v);
    l = __float2half(v - __half2float(h));
}
template<typename T>
__device__ __forceinline__ uint32_t pk2(T a, T b) {
    uint32_t u;
    uint16_t* p = (uint16_t*)&u;
    p[0] = *(uint16_t*)&a; p[1] = *(uint16_t*)&b;
    return u;
}

// ============================================================
// split GEMM on HMMA:  C[M,N] = act(A @ W + bias)
// A = (Ah,Al) [M,K] T ; B = (Bh,Bl) [N,K] T (W^T).
// PASSES==3: Ah*Bh + Al*Bh + Ah*Bl ; PASSES==1: Ah*Bh.
// BMT x 256 tile, BK=64, 256 threads; warp grid 2x4 (warp tile BMT/2 x 64).
// 2-stage cp.async double buffer; one sync per chunk. OCC = CTAs/SM hint.
// AMAX: fused per-row scaled-argmax epilogue (for the sim GEMM); emits one
//       (val, idx) candidate per row per n-tile into pv/pi instead of C.
// ============================================================
#define BN 256
#define BK 64

template<typename T, int PASSES, int BMT>
__device__ __forceinline__ void load_chunk(
    uint32_t st, const T* __restrict__ Ah, const T* __restrict__ Al,
    const T* __restrict__ Bh, const T* __restrict__ Bl,
    int m0, int n0, int k0, int K, int tid)
{
    constexpr uint32_t OFF_AL = (uint32_t)BMT * 128;
    constexpr uint32_t OFF_BH = (PASSES == 3) ? 2u * BMT * 128 : (uint32_t)BMT * 128;
    constexpr uint32_t OFF_BL = OFF_BH + 32768;
    const T* pAh = Ah + (size_t)m0 * K + k0;
    #pragma unroll
    for (int i = 0; i < BMT / 32; i++) {      // BMT rows x 8 x 16B
        int u = i * 256 + tid;
        int r = u >> 3, c = u & 7;
        uint32_t so = SWZ((uint32_t)(r * 128 + c * 16));
        size_t go = (size_t)r * K + c * 8;
        CP16(st + so, pAh + go);
        if (PASSES == 3) {
            const T* pAl = Al + (size_t)m0 * K + k0;
            CP16(st + OFF_AL + so, pAl + go);
        }
    }
    const T* pBh = Bh + (size_t)n0 * K + k0;
    #pragma unroll
    for (int i = 0; i < 8; i++) {             // B: 256 rows x 8 x 16B
        int u = i * 256 + tid;
        int r = u >> 3, c = u & 7;
        uint32_t so = SWZ((uint32_t)(r * 128 + c * 16));
        size_t go = (size_t)r * K + c * 8;
        CP16(st + OFF_BH + so, pBh + go);
        if (PASSES == 3) {
            const T* pBl = Bl + (size_t)n0 * K + k0;
            CP16(st + OFF_BL + so, pBl + go);
        }
    }
}

template<typename T, int PASSES, int BMT>
__device__ __forceinline__ void compute_chunk(
    float (&acc)[BMT / 32][8][4], uint32_t st, int wm, int wn, int g, int lr)
{
    constexpr int MT = BMT / 32;
    constexpr uint32_t OFF_AL = (uint32_t)BMT * 128;
    constexpr uint32_t OFF_BH = (PASSES == 3) ? 2u * BMT * 128 : (uint32_t)BMT * 128;
    constexpr uint32_t OFF_BL = OFF_BH + 32768;
    #pragma unroll
    for (int ks = 0; ks < 4; ks++) {
        uint32_t afh[MT * 4], afl[MT * 4], bfr[16];
        #pragma unroll
        for (int mt = 0; mt < MT; mt++) {
            int row = wm * (BMT / 2) + mt * 16 + (g & 1) * 8 + lr;
            int k   = ks * 16 + (g >> 1) * 8;
            uint32_t off = SWZ((uint32_t)(row * 128 + k * 2));
            ldsm4(&afh[mt * 4], st + off);
            if (PASSES == 3) ldsm4(&afl[mt * 4], st + OFF_AL + off);
        }
        #pragma unroll
        for (int p = 0; p < 4; p++) {
            int row = wn * 64 + (p * 2 + (g >> 1)) * 8 + lr;
            int k   = ks * 16 + (g & 1) * 8;
            uint32_t off = SWZ((uint32_t)(row * 128 + k * 2));
            ldsm4(&bfr[p * 4], st + OFF_BH + off);
        }
        #pragma unroll
        for (int mt = 0; mt < MT; mt++)
            #pragma unroll
            for (int nt = 0; nt < 8; nt++)
                mma16816<T>(acc[mt][nt], &afh[mt * 4], &bfr[(nt >> 1) * 4 + (nt & 1) * 2]);
        if (PASSES == 3) {
            #pragma unroll
            for (int mt = 0; mt < MT; mt++)
                #pragma unroll
                for (int nt = 0; nt < 8; nt++)
                    mma16816<T>(acc[mt][nt], &afl[mt * 4], &bfr[(nt >> 1) * 4 + (nt & 1) * 2]);
            #pragma unroll
            for (int p = 0; p < 4; p++) {
                int row = wn * 64 + (p * 2 + (g >> 1)) * 8 + lr;
                int k   = ks * 16 + (g & 1) * 8;
                uint32_t off = SWZ((uint32_t)(row * 128 + k * 2));
                ldsm4(&bfr[p * 4], st + OFF_BL + off);
            }
            #pragma unroll
            for (int mt = 0; mt < MT; mt++)
                #pragma unroll
                for (int nt = 0; nt < 8; nt++)
                    mma16816<T>(acc[mt][nt], &afh[mt * 4], &bfr[(nt >> 1) * 4 + (nt & 1) * 2]);
        }
    }
}

template<bool RELU, bool HASBIAS, bool WF32, bool WH, bool WLO, bool AMAX,
         int BMT, int OCC, typename T, int PASSES>
__global__ __launch_bounds__(256, OCC)
void tgemm(const T* __restrict__ Ah, const T* __restrict__ Al,
           const T* __restrict__ Bh, const T* __restrict__ Bl,
           const float* __restrict__ bias,
           float* __restrict__ oF, T* __restrict__ oH, T* __restrict__ oL,
           const float* __restrict__ pinv, float* __restrict__ pv,
           int* __restrict__ pi,
           int M, int N, int K)
{
    constexpr int MT = BMT / 32;
    constexpr uint32_t STAGE = (PASSES == 3) ? (2u * BMT * 128 + 65536)
                                             : ((uint32_t)BMT * 128 + 32768);
    extern __shared__ char smem[];
    const uint32_t sb = smem_u32(smem);
    const int tid  = threadIdx.x;
    const int wid  = tid >> 5;
    const int lane = tid & 31;
    const int wm   = wid >> 2;
    const int wn   = wid & 3;
    const int m0   = blockIdx.y * BMT;
    const int n0   = blockIdx.x * BN;
    const int NC   = K / BK;
    const int g    = lane >> 3;
    const int lr   = lane & 7;

    float acc[MT][8][4];
    #pragma unroll
    for (int i = 0; i < MT; i++)
        #pragma unroll
        for (int j = 0; j < 8; j++)
            #pragma unroll
            for (int k = 0; k < 4; k++) acc[i][j][k] = 0.f;

    load_chunk<T, PASSES, BMT>(sb, Ah, Al, Bh, Bl, m0, n0, 0, K, tid);
    CP_COMMIT();

    #pragma unroll 1
    for (int c = 0; c < NC; c++) {
        asm volatile("cp.async.wait_group 0;" ::: "memory");
        __syncthreads();
        if (c + 1 < NC)
            load_chunk<T, PASSES, BMT>(sb + ((c + 1) & 1) * STAGE,
                                       Ah, Al, Bh, Bl, m0, n0, (c + 1) * BK, K, tid);
        CP_COMMIT();
        compute_chunk<T, PASSES, BMT>(acc, sb + (c & 1) * STAGE, wm, wn, g, lr);
    }

    const int r0 = lane >> 2;
    const int c0 = (lane & 3) * 2;

    if (AMAX) {
        // ---- fused scaled-argmax epilogue: one (val,idx) per row per n-tile ----
        __syncthreads();                      // all warps done reading smem stages
        float* sval = (float*)smem;           // [BMT][4]
        int*   sidx = (int*)(smem + (size_t)BMT * 4 * sizeof(float));
        const int lgrp = lane & 3;
        #pragma unroll
        for (int mt = 0; mt < MT; mt++) {
            #pragma unroll
            for (int half = 0; half < 2; half++) {
                float bv = -3.402823466e+38f; int bidx = 0;
                #pragma unroll
                for (int nt = 0; nt < 8; nt++) {
                    int col = n0 + wn * 64 + nt * 8 + c0;
                    float v0 = acc[mt][nt][half * 2 + 0] * __ldg(&pinv[col]);
                    float v1 = acc[mt][nt][half * 2 + 1] * __ldg(&pinv[col + 1]);
                    if (v0 > bv) { bv = v0; bidx = col; }
                    if (v1 > bv) { bv = v1; bidx = col + 1; }
                }
                #pragma unroll
                for (int m = 1; m < 4; m <<= 1) {
                    float ov = __shfl_xor_sync(0xFFFFFFFFu, bv, m);
                    int   oi = __shfl_xor_sync(0xFFFFFFFFu, bidx, m);
                    if (ov > bv || (ov == bv && oi < bidx)) { bv = ov; bidx = oi; }
                }
                if (lgrp == 0) {
                    int rl = wm * (BMT / 2) + mt * 16 + r0 + half * 8;
                    sval[rl * 4 + wn] = bv;
                    sidx[rl * 4 + wn] = bidx;
                }
            }
        }
        __syncthreads();
        if (tid < BMT) {
            float bv = sval[tid * 4]; int bidx = sidx[tid * 4];
            #pragma unroll
            for (int q = 1; q < 4; q++) {
                float ov = sval[tid * 4 + q]; int oi = sidx[tid * 4 + q];
                if (ov > bv || (ov == bv && oi < bidx)) { bv = ov; bidx = oi; }
            }
            int row = m0 + tid;
            pv[row * 2 + blockIdx.x] = bv;
            pi[row * 2 + blockIdx.x] = bidx;
        }
        return;
    }

    // ---- standard epilogue ----
    #pragma unroll
    for (int nt = 0; nt < 8; nt++) {
        int col = n0 + wn * 64 + nt * 8 + c0;
        float b0 = 0.f, b1 = 0.f;
        if (HASBIAS) { b0 = __ldg(&bias[col]); b1 = __ldg(&bias[col + 1]); }
        #pragma unroll
        for (int mt = 0; mt < MT; mt++) {
            int rowa = m0 + wm * (BMT / 2) + mt * 16 + r0;
            float v0 = acc[mt][nt][0] + b0;
            float v1 = acc[mt][nt][1] + b1;
            float v2 = acc[mt][nt][2] + b0;
            float v3 = acc[mt][nt][3] + b1;
            if (RELU) {
                v0 = fmaxf(v0, 0.f); v1 = fmaxf(v1, 0.f);
                v2 = fmaxf(v2, 0.f); v3 = fmaxf(v3, 0.f);
            }
            size_t oa = (size_t)rowa * N + col;
            size_t ob = (size_t)(rowa + 8) * N + col;
            if (WF32) {
                *(float2*)(oF + oa) = make_float2(v0, v1);
                *(float2*)(oF + ob) = make_float2(v2, v3);
            }
            if (WH) {
                T h0, h1, h2, h3, l0, l1, l2, l3;
                split2<T>(v0, h0, l0); split2<T>(v1, h1, l1);
                split2<T>(v2, h2, l2); split2<T>(v3, h3, l3);
                *(uint32_t*)(oH + oa) = pk2(h0, h1);
                *(uint32_t*)(oH + ob) = pk2(h2, h3);
                if (WLO) {
                    *(uint32_t*)(oL + oa) = pk2(l0, l1);
                    *(uint32_t*)(oL + ob) = pk2(l2, l3);
                }
            }
        }
    }
}

// ============================================================
// fp32 -> (hi, lo) split, float4-vectorized (x only)
// ============================================================
__global__ __launch_bounds__(256)
void split_kernel(const float4* __restrict__ in, bf16* __restrict__ hi,
                  bf16* __restrict__ lo, int n4)
{
    int i = blockIdx.x * 256 + threadIdx.x;
    if (i >= n4) return;
    float4 v = in[i];
    bf16 h0, h1, h2, h3, l0, l1, l2, l3;
    split2<bf16>(v.x, h0, l0); split2<bf16>(v.y, h1, l1);
    split2<bf16>(v.z, h2, l2); split2<bf16>(v.w, h3, l3);
    *(uint32_t*)(hi + (size_t)i * 4)     = pk2(h0, h1);
    *(uint32_t*)(hi + (size_t)i * 4 + 2) = pk2(h2, h3);
    *(uint32_t*)(lo + (size_t)i * 4)     = pk2(l0, l1);
    *(uint32_t*)(lo + (size_t)i * 4 + 2) = pk2(l2, l3);
}

// ============================================================
// merged emb prep: split emb -> bf16 hi/lo AND inverse row norms
// ============================================================
__global__ __launch_bounds__(256)
void emb_prep_kernel(const float* __restrict__ emb, bf16* __restrict__ hi,
                     bf16* __restrict__ lo, float* __restrict__ invn)
{
    int c = blockIdx.x, t = threadIdx.x;
    float v = emb[(size_t)c * EMB + t];
    bf16 h, l;
    split2<bf16>(v, h, l);
    hi[(size_t)c * EMB + t] = h;
    lo[(size_t)c * EMB + t] = l;
    __shared__ float red[256];
    red[t] = v * v;
    __syncthreads();
    #pragma unroll
    for (int off = 128; off > 0; off >>= 1) {
        if (t < off) red[t] += red[t + off];
        __syncthreads();
    }
    if (t == 0) invn[c] = 1.f / (sqrtf(red[0]) + 1e-12f);
}

// ============================================================
// transpose + split: in [R,C] fp32 -> hi (and optionally lo) [C,R] T
// ============================================================
template<typename T, bool WANTLO>
__global__ __launch_bounds__(256)
void tsplit_kernel(const float* __restrict__ in, T* __restrict__ hi,
                   T* __restrict__ lo, int R, int C)
{
    __shared__ float t[32][33];
    int r0 = blockIdx.x * 32, c0 = blockIdx.y * 32;
    int tx = threadIdx.x, ty = threadIdx.y;
    #pragma unroll
    for (int i = 0; i < 32; i += 8)
        t[ty + i][tx] = in[(size_t)(r0 + ty + i) * C + c0 + tx];
    __syncthreads();
    #pragma unroll
    for (int i = 0; i < 32; i += 8) {
        float v = t[tx][ty + i];
        T h, l;
        split2<T>(v, h, l);
        size_t o = (size_t)(c0 + ty + i) * R + r0 + tx;
        hi[o] = h;
        if (WANTLO) lo[o] = l;
    }
}

// ============================================================
// VQ finalize: pick best of 2 per-tile candidates, write onehot + gather
// (tile0 wins ties -> lower index, matching jnp.argmax)
// ============================================================
__global__ __launch_bounds__(256)
void vq_kernel(const float* __restrict__ pv, const int* __restrict__ pi,
               const float* __restrict__ emb,
               float* __restrict__ vq_feat, float* __restrict__ onehot,
               fp16* __restrict__ vq_hi)
{
    const int w    = threadIdx.x >> 5;
    const int lane = threadIdx.x & 31;
    const int row  = blockIdx.x * 8 + w;

    float v0 = __ldg(&pv[row * 2]);
    float v1 = __ldg(&pv[row * 2 + 1]);
    int bi = (v1 > v0) ? __ldg(&pi[row * 2 + 1]) : __ldg(&pi[row * 2]);

    float* oh = onehot + (size_t)row * KCODE;
    #pragma unroll
    for (int i = 0; i < 16; i++) {
        int idx = i * 32 + lane;
        oh[idx] = (idx == bi) ? 1.f : 0.f;
    }
    const float* er = emb + (size_t)bi * EMB;
    float* vf = vq_feat + (size_t)row * EMB;
    fp16* vh = vq_hi + (size_t)row * EMB;
    #pragma unroll
    for (int i = 0; i < 8; i++) {
        int c = i * 32 + lane;
        float ev = er[c];
        vf[c] = ev;
        vh[c] = __float2half(ev);
    }
}

// ============================================================
// launcher
// ============================================================
extern "C" void kernel_launch(void* const* d_in, const int* in_sizes, int n_in,
                              void* d_out, int out_size)
{
    const float* x      = (const float*)d_in[0];
    const float* enc_w1 = (const float*)d_in[1];
    const float* enc_b1 = (const float*)d_in[2];
    const float* enc_w2 = (const float*)d_in[3];
    const float* enc_b2 = (const float*)d_in[4];
    const float* emb    = (const float*)d_in[5];
    const float* dec_w1 = (const float*)d_in[6];
    const float* dec_b1 = (const float*)d_in[7];
    const float* dec_w2 = (const float*)d_in[8];
    const float* dec_b2 = (const float*)d_in[9];

    float* out = (float*)d_out;
    float* o_encoded = out;
    float* o_vqfeat  = o_encoded + (size_t)NB * EMB;
    float* o_onehot  = o_vqfeat  + (size_t)NB * EMB;
    float* o_decoded = o_onehot  + (size_t)NB * KCODE;
    float* o_emb     = o_decoded + (size_t)NB * FEAT;

    bf16 *x_hi, *x_lo, *w1t_hi, *w1t_lo, *w2t_hi, *w2t_lo, *emb_hi, *emb_lo,
         *h_hi, *h_lo, *e_hi, *e_lo;
    fp16 *d1t_hi, *d2t_hi, *v_hi, *dd_hi;
    float *pv, *invn; int *pi;
    cudaGetSymbolAddress((void**)&x_hi, g_x_hi);     cudaGetSymbolAddress((void**)&x_lo, g_x_lo);
    cudaGetSymbolAddress((void**)&w1t_hi, g_w1t_hi); cudaGetSymbolAddress((void**)&w1t_lo, g_w1t_lo);
    cudaGetSymbolAddress((void**)&w2t_hi, g_w2t_hi); cudaGetSymbolAddress((void**)&w2t_lo, g_w2t_lo);
    cudaGetSymbolAddress((void**)&d1t_hi, g_d1t_hi);
    cudaGetSymbolAddress((void**)&d2t_hi, g_d2t_hi);
    cudaGetSymbolAddress((void**)&emb_hi, g_emb_hi); cudaGetSymbolAddress((void**)&emb_lo, g_emb_lo);
    cudaGetSymbolAddress((void**)&h_hi, g_h_hi);     cudaGetSymbolAddress((void**)&h_lo, g_h_lo);
    cudaGetSymbolAddress((void**)&e_hi, g_e_hi);     cudaGetSymbolAddress((void**)&e_lo, g_e_lo);
    cudaGetSymbolAddress((void**)&v_hi, g_v_hi);
    cudaGetSymbolAddress((void**)&dd_hi, g_dd_hi);
    cudaGetSymbolAddress((void**)&pv, g_pv);         cudaGetSymbolAddress((void**)&pi, g_pi);
    cudaGetSymbolAddress((void**)&invn, g_invn);

    const int SM_G1  = 2 * 98304;   // BMT=128 3-pass 2 stages
    const int SM_G2  = 2 * 81920;   // BMT=64  3-pass 2 stages
    const int SM_P1  = 2 * 40960;   // BMT=64  1-pass 2 stages (2 CTAs/SM)
    cudaFuncSetAttribute(tgemm<true,  true,  false, true,  true,  false, 128, 1, bf16, 3>, cudaFuncAttributeMaxDynamicSharedMemorySize, SM_G1);
    cudaFuncSetAttribute(tgemm<false, true,  true,  true,  true,  false, 64,  1, bf16, 3>, cudaFuncAttributeMaxDynamicSharedMemorySize, SM_G2);
    cudaFuncSetAttribute(tgemm<false, false, false, false, false, true,  128, 1, bf16, 3>, cudaFuncAttributeMaxDynamicSharedMemorySize, SM_G1);
    cudaFuncSetAttribute(tgemm<true,  true,  false, true,  false, false, 64,  2, fp16, 1>, cudaFuncAttributeMaxDynamicSharedMemorySize, SM_P1);
    cudaFuncSetAttribute(tgemm<true,  true,  true,  false, false, false, 64,  2, fp16, 1>, cudaFuncAttributeMaxDynamicSharedMemorySize, SM_P1);

    // launches ordered so GEMM1 is the 4th kernel launch (profiler capture slot)
    // 1) x split
    split_kernel<<<(NB * FEAT / 4) / 256, 256>>>((const float4*)x, x_hi, x_lo, NB * FEAT / 4);
    // 2) enc_w1^T split
    tsplit_kernel<bf16, true><<<dim3(FEAT / 32, MID / 32),  dim3(32, 8)>>>(enc_w1, w1t_hi, w1t_lo, FEAT, MID);
    // 3) emb split + inv norms (merged)
    emb_prep_kernel<<<KCODE, 256>>>(emb, emb_hi, emb_lo, invn);
    // 4) GEMM1: h = relu(x @ enc_w1 + b1)  [PROFILE TARGET]
    tgemm<true, true, false, true, true, false, 128, 1, bf16, 3><<<dim3(MID / BN, NB / 128), 256, SM_G1>>>(
        x_hi, x_lo, w1t_hi, w1t_lo, enc_b1, nullptr, h_hi, h_lo,
        nullptr, nullptr, nullptr, NB, MID, FEAT);
    // 5) enc_w2^T split
    tsplit_kernel<bf16, true><<<dim3(MID / 32,  EMB / 32),  dim3(32, 8)>>>(enc_w2, w2t_hi, w2t_lo, MID,  EMB);
    // 6) GEMM2 (BMT=64): encoded = h @ enc_w2 + b2
    tgemm<false, true, true, true, true, false, 64, 1, bf16, 3><<<dim3(EMB / BN, NB / 64), 256, SM_G2>>>(
        h_hi, h_lo, w2t_hi, w2t_lo, enc_b2, o_encoded, e_hi, e_lo,
        nullptr, nullptr, nullptr, NB, EMB, MID);
    // 7) sim GEMM + fused scaled-argmax -> (pv, pi) candidates
    tgemm<false, false, false, false, false, true, 128, 1, bf16, 3><<<dim3(KCODE / BN, NB / 128), 256, SM_G1>>>(
        e_hi, e_lo, emb_hi, emb_lo, nullptr, nullptr, nullptr, nullptr,
        invn, pv, pi, NB, KCODE, EMB);
    // 8) VQ finalize (warp per row: pick of 2 + onehot + gather)
    vq_kernel<<<NB / 8, 256>>>(pv, pi, emb, o_vqfeat, o_onehot, v_hi);
    // 9) dec_w1^T (fp16, hi only)
    tsplit_kernel<fp16, false><<<dim3(EMB / 32,  MID / 32),  dim3(32, 8)>>>(dec_w1, d1t_hi, nullptr, EMB,  MID);
    // 10) GEMM4: d = relu(vq @ dec_w1 + b1)  (1-pass fp16, 2 CTAs/SM)
    tgemm<true, true, false, true, false, false, 64, 2, fp16, 1><<<dim3(MID / BN, NB / 64), 256, SM_P1>>>(
        v_hi, nullptr, d1t_hi, nullptr, dec_b1, nullptr, dd_hi, nullptr,
        nullptr, nullptr, nullptr, NB, MID, EMB);
    // 11) dec_w2^T (fp16, hi only)
    tsplit_kernel<fp16, false><<<dim3(MID / 32,  FEAT / 32), dim3(32, 8)>>>(dec_w2, d2t_hi, nullptr, MID,  FEAT);
    // 12) GEMM5: decoded = relu(d @ dec_w2 + b2)  (1-pass fp16, 2 CTAs/SM)
    tgemm<true, true, true, false, false, false, 64, 2, fp16, 1><<<dim3(FEAT / BN, NB / 64), 256, SM_P1>>>(
        dd_hi, nullptr, d2t_hi, nullptr, dec_b2, o_decoded, nullptr, nullptr,
        nullptr, nullptr, nullptr, NB, FEAT, MID);
    // 13) emb passthrough
    cudaMemcpyAsync(o_emb, emb, (size_t)KCODE * EMB * sizeof(float),
                    cudaMemcpyDeviceToDevice, 0);
}